// round 1
// baseline (speedup 1.0000x reference)
#include <cuda_runtime.h>
#include <math.h>

// Problem constants
#define BB 16      // batch
#define NA 128     // audio tokens
#define TT 10      // time steps
#define NV 196     // visual patches
#define DD 256     // feature dim
#define NPAD 208   // NV padded to multiple of 16

// Scratch (device globals; no allocations allowed)
__device__ float g_a_norm[BB * NA * DD];          // 2 MB, includes 1/temperature
__device__ float g_v_norm[BB * TT * NV * DD];     // 32 MB
__device__ float g_clip_sum[BB * BB];             // sum over (a,t) of row-max
__device__ float g_negsum;                        // sum of min(s,0)^2 over all sims

// ---------------------------------------------------------------------------
// Zero the reduction scratch each launch (graph-capturable, deterministic)
// ---------------------------------------------------------------------------
__global__ void zero_kernel() {
    int tid = threadIdx.x;
    if (tid < BB * BB) g_clip_sum[tid] = 0.0f;
    if (tid == 0) g_negsum = 0.0f;
}

// ---------------------------------------------------------------------------
// L2-normalize rows of length 256; one warp per row.
// Audio variant folds 1/temperature into the normalization so the GEMM
// produces sims = dot / temperature directly.
// ---------------------------------------------------------------------------
__device__ __forceinline__ void norm_row(const float* __restrict__ in,
                                         float* __restrict__ out,
                                         int row, int lane, float scale) {
    const float4* src = reinterpret_cast<const float4*>(in) + (size_t)row * (DD / 4);
    float4 v0 = src[lane];
    float4 v1 = src[lane + 32];
    float ss = v0.x * v0.x + v0.y * v0.y + v0.z * v0.z + v0.w * v0.w
             + v1.x * v1.x + v1.y * v1.y + v1.z * v1.z + v1.w * v1.w;
#pragma unroll
    for (int off = 16; off >= 1; off >>= 1)
        ss += __shfl_xor_sync(0xffffffffu, ss, off);
    float inv = scale / fmaxf(sqrtf(ss), 1e-12f);
    v0.x *= inv; v0.y *= inv; v0.z *= inv; v0.w *= inv;
    v1.x *= inv; v1.y *= inv; v1.z *= inv; v1.w *= inv;
    float4* dst = reinterpret_cast<float4*>(out) + (size_t)row * (DD / 4);
    dst[lane]      = v0;
    dst[lane + 32] = v1;
}

__global__ void norm_audio_kernel(const float* __restrict__ in,
                                  const float* __restrict__ temp_ptr) {
    int warp = (blockIdx.x * blockDim.x + threadIdx.x) >> 5;
    int lane = threadIdx.x & 31;
    if (warp >= BB * NA) return;
    float scale = 1.0f / (*temp_ptr);
    norm_row(in, g_a_norm, warp, lane, scale);
}

__global__ void norm_visual_kernel(const float* __restrict__ in) {
    int warp = (blockIdx.x * blockDim.x + threadIdx.x) >> 5;
    int lane = threadIdx.x & 31;
    if (warp >= BB * TT * NV) return;
    norm_row(in, g_v_norm, warp, lane, 1.0f);
}

// ---------------------------------------------------------------------------
// Main kernel: one block per (x, y, t).
// Computes S = A_x (128 x 256) . V_{y,t}^T (256 x 196), fused epilogue:
//   per-row max over the 196 patches  -> accumulated into g_clip_sum[x,y]
//   sum of min(s,0)^2 over all valid  -> accumulated into g_negsum
// Register tile: 256 threads as 16x16, each thread 8 rows x 13 cols.
// ---------------------------------------------------------------------------
__global__ __launch_bounds__(256, 1) void sim_kernel() {
    const int x = blockIdx.x;
    const int y = blockIdx.y;
    const int t = blockIdx.z;

    __shared__ float As[32][132];   // [k][m], padded to break bank conflicts
    __shared__ float Bs[32][212];   // [k][n]
    __shared__ float red[256];
    __shared__ float red2[16];

    const float* __restrict__ Ag = g_a_norm + (size_t)x * NA * DD;
    const float* __restrict__ Bg = g_v_norm + ((size_t)y * TT + t) * NV * DD;

    const int tid = threadIdx.x;
    const int tx = tid & 15;    // col group
    const int ty = tid >> 4;    // row group (rows ty*8 .. ty*8+7)

    float acc[8][13];
#pragma unroll
    for (int i = 0; i < 8; i++)
#pragma unroll
        for (int j = 0; j < 13; j++) acc[i][j] = 0.0f;

    for (int k0 = 0; k0 < DD; k0 += 32) {
        __syncthreads();
        // Load A tile: 128 rows x 32 k, transposed into As[k][m]
#pragma unroll
        for (int l = 0; l < 4; l++) {
            int idx = tid + l * 256;        // float4 index among 1024
            int m  = idx >> 3;              // 8 float4 per row-chunk
            int kk = (idx & 7) << 2;
            float4 v = *reinterpret_cast<const float4*>(Ag + m * DD + k0 + kk);
            As[kk + 0][m] = v.x; As[kk + 1][m] = v.y;
            As[kk + 2][m] = v.z; As[kk + 3][m] = v.w;
        }
        // Load B tile: 196 rows (pad to 208 with zeros) x 32 k into Bs[k][n]
        for (int idx = tid; idx < NPAD * 8; idx += 256) {
            int n  = idx >> 3;
            int kk = (idx & 7) << 2;
            float4 v = (n < NV)
                ? *reinterpret_cast<const float4*>(Bg + n * DD + k0 + kk)
                : make_float4(0.f, 0.f, 0.f, 0.f);
            Bs[kk + 0][n] = v.x; Bs[kk + 1][n] = v.y;
            Bs[kk + 2][n] = v.z; Bs[kk + 3][n] = v.w;
        }
        __syncthreads();

#pragma unroll 2
        for (int k = 0; k < 32; k++) {
            float4 A0 = *reinterpret_cast<const float4*>(&As[k][ty * 8]);
            float4 A1 = *reinterpret_cast<const float4*>(&As[k][ty * 8 + 4]);
            float a[8] = {A0.x, A0.y, A0.z, A0.w, A1.x, A1.y, A1.z, A1.w};
            float b[13];
#pragma unroll
            for (int j = 0; j < 13; j++) b[j] = Bs[k][tx + 16 * j];
#pragma unroll
            for (int i = 0; i < 8; i++)
#pragma unroll
                for (int j = 0; j < 13; j++)
                    acc[i][j] = fmaf(a[i], b[j], acc[i][j]);
        }
    }

    // ---- fused epilogue ----
    float negsum = 0.0f;
    float rmax[8];
#pragma unroll
    for (int i = 0; i < 8; i++) rmax[i] = -1e30f;
#pragma unroll
    for (int j = 0; j < 13; j++) {
        int col = tx + 16 * j;
        if (col < NV) {
#pragma unroll
            for (int i = 0; i < 8; i++) {
                float s = acc[i][j];
                rmax[i] = fmaxf(rmax[i], s);
                float ng = fminf(s, 0.0f);
                negsum = fmaf(ng, ng, negsum);
            }
        }
    }
    // reduce row-max across the 16 tx lanes (xor<16 keeps groups separate)
#pragma unroll
    for (int off = 8; off >= 1; off >>= 1) {
#pragma unroll
        for (int i = 0; i < 8; i++)
            rmax[i] = fmaxf(rmax[i], __shfl_xor_sync(0xffffffffu, rmax[i], off));
    }
    float rowsum = 0.0f;
#pragma unroll
    for (int i = 0; i < 8; i++) rowsum += rmax[i];

    __syncthreads();   // done reading As/Bs; now reuse barrier for reductions
    red[tid] = negsum;
    if (tx == 0) red2[ty] = rowsum;
    __syncthreads();
    for (int s = 128; s >= 1; s >>= 1) {
        if (tid < s) red[tid] += red[tid + s];
        __syncthreads();
    }
    if (tid == 0) {
        float rs = 0.0f;
        for (int i = 0; i < 16; i++) rs += red2[i];
        atomicAdd(&g_clip_sum[x * BB + y], rs);
        atomicAdd(&g_negsum, red[0]);
    }
}

// ---------------------------------------------------------------------------
// Finalize: 16x16 clip sims -> InfoNCE + regularization -> 3 scalars
// ---------------------------------------------------------------------------
__global__ void finalize_kernel(const float* __restrict__ temp_ptr,
                                float* __restrict__ out, int out_size) {
    __shared__ float cs[BB][BB];
    __shared__ float lr[BB], lc[BB];
    int tid = threadIdx.x;
    if (tid < BB * BB)
        cs[tid >> 4][tid & 15] = g_clip_sum[tid] * (1.0f / (float)(NA * TT));
    __syncthreads();
    if (tid < BB) {
        int i = tid;
        float m = -1e30f, mc = -1e30f;
        for (int j = 0; j < BB; j++) { m = fmaxf(m, cs[i][j]); mc = fmaxf(mc, cs[j][i]); }
        float s = 0.0f, sc = 0.0f;
        for (int j = 0; j < BB; j++) { s += expf(cs[i][j] - m); sc += expf(cs[j][i] - mc); }
        lr[i] = m + logf(s);
        lc[i] = mc + logf(sc);
    }
    __syncthreads();
    if (tid == 0) {
        float lsum = 0.0f;
        for (int i = 0; i < BB; i++)
            lsum += -(cs[i][i] - lr[i]) - (cs[i][i] - lc[i]);
        float contrastive = 0.5f * (lsum / (float)BB);
        float l_nonneg = g_negsum
            / ((float)BB * (float)BB * (float)NA * (float)TT * (float)NV);
        float tv = *temp_ptr;
        float logt = logf(tv);
        float tl = fmaxf(-logt, 0.0f);            tl = tl * tl; tl = tl * tl;
        float th = fmaxf(logt - logf(3.0f), 0.0f); th = th * th; th = th * th;
        float reg = l_nonneg + tl + th;
        float total = contrastive + 0.3f * reg;
        out[0] = total;
        if (out_size > 1) out[1] = contrastive;
        if (out_size > 2) out[2] = reg;
    }
}

// ---------------------------------------------------------------------------
extern "C" void kernel_launch(void* const* d_in, const int* in_sizes, int n_in,
                              void* d_out, int out_size) {
    const float* audio  = (const float*)d_in[0];   // (16,128,256) f32
    const float* visual = (const float*)d_in[1];   // (16,10,196,256) f32
    const float* temp   = (const float*)d_in[2];   // scalar f32
    float* out = (float*)d_out;

    zero_kernel<<<1, 256>>>();
    norm_audio_kernel<<<(BB * NA) / 8, 256>>>(audio, temp);        // 256 blocks
    norm_visual_kernel<<<(BB * TT * NV) / 8, 256>>>(visual);       // 3920 blocks
    dim3 grid(BB, BB, TT);
    sim_kernel<<<grid, 256>>>();
    finalize_kernel<<<1, 256>>>(temp, out, out_size);
}

// round 3
// speedup vs baseline: 8.0889x; 8.0889x over previous
#include <cuda_runtime.h>
#include <cuda_bf16.h>
#include <math.h>
#include <stdint.h>

// Problem constants
#define BB 16      // batch
#define NA 128     // audio tokens
#define TT 10      // time steps
#define NV 196     // visual patches
#define DD 256     // feature dim
#define NPAD 208   // NV padded to multiple of 16

// Padded K stride (bf16 elements) to make ldmatrix conflict-free: 264*2=528B
#define KP 264
#define ROWB 528

// SMEM layout (bytes, dynamic)
#define OFF_A    0
#define OFF_B    67584                        // 128*528
#define OFF_RMAX 177408                       // + 208*528
#define OFF_NEG  (OFF_RMAX + 2*128*4)
#define SMEM_DYN (OFF_NEG + 8*4 + 32)

// ---------------------------------------------------------------------------
// Device scratch (no allocations allowed)
// ---------------------------------------------------------------------------
__device__ __nv_bfloat16 g_a_bf16[BB * NA * DD];       // normalized audio (incl 1/T)
__device__ __nv_bfloat16 g_v_bf16[BB * TT * NV * DD];  // normalized visual
__device__ float g_clip_sum[BB * BB];
__device__ float g_negsum;

// ---------------------------------------------------------------------------
__device__ __forceinline__ uint32_t smem_u32(const void* p) {
    uint32_t a;
    asm("{ .reg .u64 t; cvta.to.shared.u64 t, %1; cvt.u32.u64 %0, t; }" : "=r"(a) : "l"(p));
    return a;
}

__device__ __forceinline__ void ldsm4(uint32_t* r, uint32_t addr) {
    asm volatile("ldmatrix.sync.aligned.m8n8.x4.shared.b16 {%0,%1,%2,%3}, [%4];"
                 : "=r"(r[0]), "=r"(r[1]), "=r"(r[2]), "=r"(r[3]) : "r"(addr));
}
__device__ __forceinline__ void ldsm2(uint32_t* r, uint32_t addr) {
    asm volatile("ldmatrix.sync.aligned.m8n8.x2.shared.b16 {%0,%1}, [%2];"
                 : "=r"(r[0]), "=r"(r[1]) : "r"(addr));
}
__device__ __forceinline__ void mma_bf16(float* d, const uint32_t* a, const uint32_t* b) {
    asm volatile(
        "mma.sync.aligned.m16n8k16.row.col.f32.bf16.bf16.f32 "
        "{%0,%1,%2,%3}, {%4,%5,%6,%7}, {%8,%9}, {%0,%1,%2,%3};"
        : "+f"(d[0]), "+f"(d[1]), "+f"(d[2]), "+f"(d[3])
        : "r"(a[0]), "r"(a[1]), "r"(a[2]), "r"(a[3]), "r"(b[0]), "r"(b[1]));
}

// ---------------------------------------------------------------------------
__global__ void zero_kernel() {
    int tid = threadIdx.x;
    if (tid < BB * BB) g_clip_sum[tid] = 0.0f;
    if (tid == 0) g_negsum = 0.0f;
}

// ---------------------------------------------------------------------------
// L2-normalize one 256-elem row per warp; write bf16. scale folds 1/temperature.
// ---------------------------------------------------------------------------
__device__ __forceinline__ void norm_row_bf16(const float* __restrict__ in,
                                              __nv_bfloat16* __restrict__ out,
                                              long row, int lane, float scale) {
    const float4* src = reinterpret_cast<const float4*>(in + row * DD);
    float4 v0 = src[lane * 2];
    float4 v1 = src[lane * 2 + 1];
    float ss = v0.x*v0.x + v0.y*v0.y + v0.z*v0.z + v0.w*v0.w
             + v1.x*v1.x + v1.y*v1.y + v1.z*v1.z + v1.w*v1.w;
#pragma unroll
    for (int off = 16; off >= 1; off >>= 1)
        ss += __shfl_xor_sync(0xffffffffu, ss, off);
    float inv = scale / fmaxf(sqrtf(ss), 1e-12f);
    __nv_bfloat162 h[4];
    h[0] = __floats2bfloat162_rn(v0.x * inv, v0.y * inv);
    h[1] = __floats2bfloat162_rn(v0.z * inv, v0.w * inv);
    h[2] = __floats2bfloat162_rn(v1.x * inv, v1.y * inv);
    h[3] = __floats2bfloat162_rn(v1.z * inv, v1.w * inv);
    reinterpret_cast<uint4*>(out + row * DD)[lane] = *reinterpret_cast<uint4*>(h);
}

__global__ void norm_audio_kernel(const float* __restrict__ in,
                                  const float* __restrict__ temp_ptr) {
    long warp = (blockIdx.x * (long)blockDim.x + threadIdx.x) >> 5;
    int lane = threadIdx.x & 31;
    if (warp >= BB * NA) return;
    float scale = 1.0f / (*temp_ptr);
    norm_row_bf16(in, g_a_bf16, warp, lane, scale);
}

__global__ void norm_visual_kernel(const float* __restrict__ in) {
    long warp = (blockIdx.x * (long)blockDim.x + threadIdx.x) >> 5;
    int lane = threadIdx.x & 31;
    if (warp >= BB * TT * NV) return;
    norm_row_bf16(in, g_v_bf16, warp, lane, 1.0f);
}

// ---------------------------------------------------------------------------
// Main: one block per (x,y,t). ldmatrix + mma.sync bf16, 128 x 208 x 256.
// 8 warps: 4 (M) x 2 (N); warp tile 32 x 104 = 2 x 13 m16n8k16 tiles.
// Fused epilogue: per-row max over 196 patches, sum of min(s,0)^2.
// ---------------------------------------------------------------------------
__global__ __launch_bounds__(256, 1) void sim_kernel() {
    extern __shared__ char sm[];
    const uint32_t sbase = smem_u32(sm);

    const int x = blockIdx.x, y = blockIdx.y, t = blockIdx.z;
    const int tid  = threadIdx.x;
    const int wid  = tid >> 5, lane = tid & 31;
    const int wm   = wid & 3;          // M group: rows wm*32..+31
    const int wn   = wid >> 2;         // N group: cols wn*104..+103
    const int gid  = lane >> 2;        // group id (0-7)
    const int tig  = lane & 3;         // thread in group

    // ---- fill A tile: 128 x 256 bf16 -> smem rows of 528B ----
    const uint4* a_src = reinterpret_cast<const uint4*>(g_a_bf16) + (size_t)x * NA * (DD / 8);
#pragma unroll
    for (int c = tid; c < NA * 32; c += 256) {
        int row = c >> 5, k8 = c & 31;
        uint4 v = a_src[c];
        *reinterpret_cast<uint4*>(sm + OFF_A + row * ROWB + k8 * 16) = v;
    }
    // ---- fill B tile: 208 rows (196 real + zero pad) x 256 bf16 ----
    const uint4* v_src = reinterpret_cast<const uint4*>(g_v_bf16)
                       + (size_t)(y * TT + t) * NV * (DD / 8);
#pragma unroll
    for (int c = tid; c < NPAD * 32; c += 256) {
        int n = c >> 5, k8 = c & 31;
        uint4 v = (n < NV) ? v_src[c] : make_uint4(0u, 0u, 0u, 0u);
        *reinterpret_cast<uint4*>(sm + OFF_B + n * ROWB + k8 * 16) = v;
    }
    __syncthreads();

    // ---- ldmatrix lane base addresses ----
    // A: lanes 0-15 rows (wm*32 + l), khalf 0; lanes 16-31 same rows, khalf 8
    uint32_t aAddr = sbase + OFF_A
                   + (uint32_t)(wm * 32 + (lane & 15)) * ROWB
                   + (uint32_t)((lane >> 4) * 16);
    // B pair-tile: n = wn*104 + (lane&7) + ((lane>>4)&1)*8 ; khalf = ((lane>>3)&1)*8
    uint32_t bAddr = sbase + OFF_B
                   + (uint32_t)(wn * 104 + (lane & 7) + ((lane >> 4) & 1) * 8) * ROWB
                   + (uint32_t)(((lane >> 3) & 1) * 16);
    // B last single tile (j=12): lanes 0-7 n=+96+(l&7) kh 0 ; 8-15 kh 8
    uint32_t bAddr2 = sbase + OFF_B
                    + (uint32_t)(wn * 104 + 96 + (lane & 7)) * ROWB
                    + (uint32_t)(((lane >> 3) & 1) * 16);

    float acc[2][13][4];
#pragma unroll
    for (int mt = 0; mt < 2; mt++)
#pragma unroll
        for (int j = 0; j < 13; j++)
#pragma unroll
            for (int q = 0; q < 4; q++) acc[mt][j][q] = 0.0f;

#pragma unroll 4
    for (int ks = 0; ks < 16; ks++) {
        const uint32_t koff = (uint32_t)ks * 32;   // 16 bf16 = 32B per k-step
        uint32_t a0[4], a1[4];
        ldsm4(a0, aAddr + koff);               // m-tile 0 (rows wm*32+0..15)
        ldsm4(a1, aAddr + koff + 16 * ROWB);   // m-tile 1 (rows +16..31)
#pragma unroll
        for (int jp = 0; jp < 6; jp++) {
            uint32_t b[4];
            ldsm4(b, bAddr + koff + (uint32_t)jp * (16 * ROWB));
            mma_bf16(acc[0][2 * jp],     a0, b);
            mma_bf16(acc[0][2 * jp + 1], a0, b + 2);
            mma_bf16(acc[1][2 * jp],     a1, b);
            mma_bf16(acc[1][2 * jp + 1], a1, b + 2);
        }
        uint32_t bl[2];
        ldsm2(bl, bAddr2 + koff);
        mma_bf16(acc[0][12], a0, bl);
        mma_bf16(acc[1][12], a1, bl);
    }

    // ---- fused epilogue ----
    float rmax[2][2] = {{-1e30f, -1e30f}, {-1e30f, -1e30f}};
    float negsum = 0.0f;
#pragma unroll
    for (int mt = 0; mt < 2; mt++) {
#pragma unroll
        for (int j = 0; j < 13; j++) {
            int col = wn * 104 + j * 8 + tig * 2;
            float c0 = acc[mt][j][0], c1 = acc[mt][j][1];
            float c2 = acc[mt][j][2], c3 = acc[mt][j][3];
            // pad columns hold exact 0 -> contribute 0 to negsum
            float n0 = fminf(c0, 0.0f), n1 = fminf(c1, 0.0f);
            float n2 = fminf(c2, 0.0f), n3 = fminf(c3, 0.0f);
            negsum = fmaf(n0, n0, negsum); negsum = fmaf(n1, n1, negsum);
            negsum = fmaf(n2, n2, negsum); negsum = fmaf(n3, n3, negsum);
            if (col < NV)     { rmax[mt][0] = fmaxf(rmax[mt][0], c0);
                                rmax[mt][1] = fmaxf(rmax[mt][1], c2); }
            if (col + 1 < NV) { rmax[mt][0] = fmaxf(rmax[mt][0], c1);
                                rmax[mt][1] = fmaxf(rmax[mt][1], c3); }
        }
    }
    // reduce row-max across the 4 lanes of each group (they hold different cols)
#pragma unroll
    for (int off = 1; off <= 2; off <<= 1) {
#pragma unroll
        for (int mt = 0; mt < 2; mt++) {
            rmax[mt][0] = fmaxf(rmax[mt][0], __shfl_xor_sync(0xffffffffu, rmax[mt][0], off));
            rmax[mt][1] = fmaxf(rmax[mt][1], __shfl_xor_sync(0xffffffffu, rmax[mt][1], off));
        }
    }
    // full warp reduce negsum
#pragma unroll
    for (int off = 16; off >= 1; off >>= 1)
        negsum += __shfl_xor_sync(0xffffffffu, negsum, off);

    float* rowmax = reinterpret_cast<float*>(sm + OFF_RMAX);   // [2][128]
    float* negs   = reinterpret_cast<float*>(sm + OFF_NEG);    // [8]
    if (tig == 0) {
#pragma unroll
        for (int mt = 0; mt < 2; mt++) {
            int r = wm * 32 + mt * 16 + gid;
            rowmax[wn * 128 + r]     = rmax[mt][0];
            rowmax[wn * 128 + r + 8] = rmax[mt][1];
        }
    }
    if (lane == 0) negs[wid] = negsum;
    __syncthreads();

    // combine halves + block sum
    if (tid < 128)
        rowmax[tid] = fmaxf(rowmax[tid], rowmax[128 + tid]);
    __syncthreads();
#pragma unroll
    for (int s = 64; s >= 1; s >>= 1) {
        if (tid < s) rowmax[tid] += rowmax[tid + s];
        __syncthreads();
    }
    if (tid == 0) {
        float ns = 0.0f;
#pragma unroll
        for (int i = 0; i < 8; i++) ns += negs[i];
        atomicAdd(&g_clip_sum[x * BB + y], rowmax[0]);
        atomicAdd(&g_negsum, ns);
    }
}

// ---------------------------------------------------------------------------
// Finalize: 16x16 clip sims -> InfoNCE + regularization -> 3 scalars
// ---------------------------------------------------------------------------
__global__ void finalize_kernel(const float* __restrict__ temp_ptr,
                                float* __restrict__ out, int out_size) {
    __shared__ float cs[BB][BB];
    __shared__ float lr[BB], lc[BB];
    int tid = threadIdx.x;
    if (tid < BB * BB)
        cs[tid >> 4][tid & 15] = g_clip_sum[tid] * (1.0f / (float)(NA * TT));
    __syncthreads();
    if (tid < BB) {
        int i = tid;
        float m = -1e30f, mc = -1e30f;
        for (int j = 0; j < BB; j++) { m = fmaxf(m, cs[i][j]); mc = fmaxf(mc, cs[j][i]); }
        float s = 0.0f, sc = 0.0f;
        for (int j = 0; j < BB; j++) { s += expf(cs[i][j] - m); sc += expf(cs[j][i] - mc); }
        lr[i] = m + logf(s);
        lc[i] = mc + logf(sc);
    }
    __syncthreads();
    if (tid == 0) {
        float lsum = 0.0f;
        for (int i = 0; i < BB; i++)
            lsum += -(cs[i][i] - lr[i]) - (cs[i][i] - lc[i]);
        float contrastive = 0.5f * (lsum / (float)BB);
        float l_nonneg = g_negsum
            / ((float)BB * (float)BB * (float)NA * (float)TT * (float)NV);
        float tv = *temp_ptr;
        float logt = logf(tv);
        float tl = fmaxf(-logt, 0.0f);             tl = tl * tl; tl = tl * tl;
        float th = fmaxf(logt - logf(3.0f), 0.0f); th = th * th; th = th * th;
        float reg = l_nonneg + tl + th;
        float total = contrastive + 0.3f * reg;
        out[0] = total;
        if (out_size > 1) out[1] = contrastive;
        if (out_size > 2) out[2] = reg;
    }
}

// ---------------------------------------------------------------------------
extern "C" void kernel_launch(void* const* d_in, const int* in_sizes, int n_in,
                              void* d_out, int out_size) {
    const float* audio  = (const float*)d_in[0];   // (16,128,256) f32
    const float* visual = (const float*)d_in[1];   // (16,10,196,256) f32
    const float* temp   = (const float*)d_in[2];   // scalar f32
    float* out = (float*)d_out;

    cudaFuncSetAttribute(sim_kernel, cudaFuncAttributeMaxDynamicSharedMemorySize, SMEM_DYN);

    zero_kernel<<<1, 256>>>();
    norm_audio_kernel<<<(BB * NA) / 8, 256>>>(audio, temp);
    norm_visual_kernel<<<(BB * TT * NV) / 8, 256>>>(visual);
    dim3 grid(BB, BB, TT);
    sim_kernel<<<grid, 256, SMEM_DYN>>>();
    finalize_kernel<<<1, 256>>>(temp, out, out_size);
}